// round 5
// baseline (speedup 1.0000x reference)
#include <cuda_runtime.h>

#define NTRIP 55
#define DTOT  404480
#define EPSV  1e-6f
#define NKB   1580
#define KSPAN 256

__device__ int   d_l1[NTRIP], d_l2[NTRIP], d_l3a[NTRIP], d_widx[NTRIP], d_based[NTRIP];
__device__ int   d_cnt[9];
__device__ float d_sumsq[64 * 9];
__device__ float d_sum0[64];
__device__ float d_A[64 * 9];
__device__ float d_D0[64];
__device__ float d_y[64 * 800];                  // per-b: l-offsets 0,32,128,288,512; each block o*(2l+1)+m
__device__ float d_z[64LL * DTOT];
__device__ float d_part[(long)NKB * 8192];

// ------------- setup: triple tables (sorted by l3, stable in TRIPLES order) + zero stats -------------
__global__ void k_setup() {
    int t = threadIdx.x;
    if (t == 0) {
        int L1[NTRIP], L2[NTRIP], L3[NTRIP], n = 0;
        for (int l1 = 0; l1 <= 4; l1++)
            for (int l2 = l1; l2 <= 4; l2++)
                for (int l3 = l2 - l1; l3 <= l1 + l2; l3++) { L1[n]=l1; L2[n]=l2; L3[n]=l3; n++; }
        int idx = 0, based = 0;
        for (int lv = 0; lv <= 8; lv++) {
            int c = 0;
            for (int s = 0; s < n; s++) if (L3[s] == lv) {
                d_l1[idx]=L1[s]; d_l2[idx]=L2[s]; d_l3a[idx]=lv; d_widx[idx]=s; d_based[idx]=based;
                based += 1024 * (2*lv + 1); idx++; c++;
            }
            d_cnt[lv] = c * 1024 * (2*lv + 1);
        }
    }
    for (int i = t; i < 64*9; i += blockDim.x) d_sumsq[i] = 0.f;
    for (int i = t; i < 64;   i += blockDim.x) d_sum0[i]  = 0.f;
}

// ------------- y[l] = einsum('bim,oi->bom') (+bias0 on l=0) -------------
__global__ void k_y(const float* __restrict__ x0, const float* __restrict__ x1,
                    const float* __restrict__ x2, const float* __restrict__ x3,
                    const float* __restrict__ x4, const float* __restrict__ Wlin,
                    const float* __restrict__ bias0) {
    int b = blockIdx.x;
    const float* xs[5] = {x0, x1, x2, x3, x4};
    const int yo[5] = {0, 32, 128, 288, 512};   // cumulative 32*(2l+1): 32,96,160,224,288
    for (int l = 0; l < 5; l++) {
        int M = 2*l + 1;
        const float* x = xs[l] + (long)b * 32 * M;
        for (int e = threadIdx.x; e < 32 * M; e += blockDim.x) {
            int o = e / M, m = e % M;
            float acc = (l == 0) ? bias0[o] : 0.f;
            const float* wr = Wlin + (l*32 + o) * 32;
            #pragma unroll 8
            for (int i = 0; i < 32; i++) acc += wr[i] * x[i*M + m];
            d_y[b*800 + yo[l] + o*M + m] = acc;
        }
    }
}

// ------------- triple products + row-norm + LN stats -------------
template <int K3>
__global__ void __launch_bounds__(256) k_trip(const float* __restrict__ w3j, int troff) {
    const int tr = troff + blockIdx.x, b = blockIdx.y;
    const int l3v = (K3 - 1) / 2;
    const int l1 = d_l1[tr], l2 = d_l2[tr];
    const int m1 = 2*l1 + 1, n2 = 2*l2 + 1;
    __shared__ float sy1[288], sy2[288], sw[1377], su[4896], r1[256], r2[256];
    const int yo[5] = {0, 32, 128, 288, 512};
    int t = threadIdx.x;

    for (int e = t; e < 32*m1; e += 256) sy1[e] = d_y[b*800 + yo[l1] + e];
    for (int e = t; e < 32*n2; e += 256) sy2[e] = d_y[b*800 + yo[l2] + e];
    const float* wp = w3j + (long)d_widx[tr] * 9 * 9 * 17;
    for (int e = t; e < m1*n2*K3; e += 256) {
        int m = e / (n2*K3), r = e % (n2*K3), nn = r / K3, k = r % K3;
        sw[e] = wp[m*153 + nn*17 + k];
    }
    __syncthreads();
    // u[j,m,k] = sum_n y2[j,n] * w[m,n,k]
    for (int e = t; e < 32*m1*K3; e += 256) {
        int j = e / (m1*K3), r = e % (m1*K3), m = r / K3, k = r % K3;
        float a = 0.f;
        for (int nn = 0; nn < n2; nn++) a += sy2[j*n2 + nn] * sw[(m*n2 + nn)*K3 + k];
        su[e] = a;
    }
    __syncthreads();

    float lsq = 0.f, ls0 = 0.f;
    long zbase = (long)b * DTOT + d_based[tr];
    for (int p = t; p < 1024; p += 256) {
        int i = p >> 5, j = p & 31;
        float acc[K3];
        #pragma unroll
        for (int k = 0; k < K3; k++) acc[k] = 0.f;
        const float* y1p = &sy1[i*m1];
        for (int m = 0; m < m1; m++) {
            float ym = y1p[m];
            const float* up = &su[(j*m1 + m)*K3];
            #pragma unroll
            for (int k = 0; k < K3; k++) acc[k] += ym * up[k];
        }
        float S = 0.f;
        #pragma unroll
        for (int k = 0; k < K3; k++) S += acc[k]*acc[k];
        float inv = rsqrtf(S + EPSV);
        float* zp = &d_z[zbase + (long)p * K3];
        #pragma unroll
        for (int k = 0; k < K3; k++) zp[k] = acc[k] * inv;
        lsq += S * inv * inv;
        if (K3 == 1) ls0 += acc[0] * inv;
    }
    r1[t] = lsq; r2[t] = ls0;
    __syncthreads();
    for (int s = 128; s > 0; s >>= 1) {
        if (t < s) { r1[t] += r1[t+s]; r2[t] += r2[t+s]; }
        __syncthreads();
    }
    if (t == 0) {
        atomicAdd(&d_sumsq[b*9 + l3v], r1[0]);
        if (K3 == 1) atomicAdd(&d_sum0[b], r2[0]);
    }
}

// ------------- per-(b,l3) scalars: power-scale + LN folded into affine A,D -------------
__global__ void k_scal() {
    int b = threadIdx.x;
    if (b >= 64) return;
    float power = 0.f;
    for (int l = 0; l < 9; l++) power += d_sumsq[b*9 + l];
    float scale = rsqrtf(power / (float)DTOT + EPSV);
    for (int l = 0; l < 9; l++) {
        float ms = scale * scale * d_sumsq[b*9 + l] / (float)d_cnt[l];
        if (l == 0) {
            float mu  = scale * d_sum0[b] / (float)d_cnt[0];
            float c   = rsqrtf(ms - mu*mu + EPSV);
            d_A[b*9]  = scale * c;
            d_D0[b]   = -mu * c;
        } else {
            d_A[b*9 + l] = scale * rsqrtf(ms + EPSV);
        }
    }
}

// ------------- BN across batch (stats per (triple,i,j)) + in-place rewrite -------------
__global__ void __launch_bounds__(256) k_bn() {
    int tr = blockIdx.x >> 5, i = blockIdx.x & 31;
    int l3v = d_l3a[tr], k3 = 2*l3v + 1, E = 32 * k3;
    long base = (long)d_based[tr] + (long)i * E;
    __shared__ float sA[64], sD[64], ssq[544], ssum[544], sg[32], sm2[32];
    int t = threadIdx.x;
    if (t < 64) { sA[t] = d_A[t*9 + l3v]; sD[t] = (l3v == 0) ? d_D0[t] : 0.f; }
    __syncthreads();
    for (int e = t; e < E; e += 256) {
        float asq = 0.f, asum = 0.f;
        for (int b = 0; b < 64; b++) {
            float v = sA[b] * d_z[(long)b*DTOT + base + e] + sD[b];
            asq += v*v; asum += v;
        }
        ssq[e] = asq; ssum[e] = asum;
    }
    __syncthreads();
    if (t < 32) {
        float sq = 0.f, sm = 0.f;
        for (int k = 0; k < k3; k++) { sq += ssq[t*k3 + k]; sm += ssum[t*k3 + k]; }
        if (l3v == 0) {
            float m = sm * (1.f/64.f);
            sg[t] = rsqrtf(sq*(1.f/64.f) - m*m + EPSV); sm2[t] = m;
        } else {
            sg[t] = rsqrtf(sq / (64.f * (float)k3) + EPSV); sm2[t] = 0.f;
        }
    }
    __syncthreads();
    for (int e = t; e < E; e += 256) {
        int j = e / k3;
        float g = sg[j], mm = sm2[j];
        for (int b = 0; b < 64; b++) {
            long idx = (long)b*DTOT + base + e;
            d_z[idx] = (sA[b]*d_z[idx] + sD[b] - mm) * g;
        }
    }
}

// ------------- split-K GEMM: lat = z @ W_fc^T via packed f32x2 FFMA -------------
__device__ __forceinline__ unsigned long long pk2(float x, float y) {
    unsigned long long r;
    asm("mov.b64 %0, {%1, %2};" : "=l"(r) : "f"(x), "f"(y));
    return r;
}
__device__ __forceinline__ unsigned long long ffma2(unsigned long long a, unsigned long long b,
                                                    unsigned long long c) {
    unsigned long long d;
    asm("fma.rn.f32x2 %0, %1, %2, %3;" : "=l"(d) : "l"(a), "l"(b), "l"(c));
    return d;
}

__global__ void __launch_bounds__(256) k_gemm(const float* __restrict__ W) {
    __shared__ __align__(16) float As[32][68];
    __shared__ __align__(16) float Bs[32][132];
    int t = threadIdx.x, ty = t >> 4, tx = t & 15;
    long kbase = (long)blockIdx.x * KSPAN;
    unsigned long long acc[4][4];
    #pragma unroll
    for (int a = 0; a < 4; a++)
        #pragma unroll
        for (int p = 0; p < 4; p++) acc[a][p] = 0ULL;

    for (int c = 0; c < KSPAN/32; c++) {
        long kg = kbase + c*32;
        #pragma unroll
        for (int r = 0; r < 8; r++) {
            int q = t + r*256, row = q >> 5, kk = q & 31;
            As[kk][row] = d_z[(long)row*DTOT + kg + kk];
        }
        #pragma unroll
        for (int r = 0; r < 16; r++) {
            int q = t + r*256, row = q >> 5, kk = q & 31;
            Bs[kk][row] = W[(long)row*DTOT + kg + kk];
        }
        __syncthreads();
        #pragma unroll 8
        for (int k = 0; k < 32; k++) {
            float4 av = *(const float4*)&As[k][ty*4];
            ulonglong2 b0 = *(const ulonglong2*)&Bs[k][tx*8];
            ulonglong2 b1 = *(const ulonglong2*)&Bs[k][tx*8 + 4];
            unsigned long long a0 = pk2(av.x, av.x), a1 = pk2(av.y, av.y);
            unsigned long long a2 = pk2(av.z, av.z), a3 = pk2(av.w, av.w);
            acc[0][0]=ffma2(a0,b0.x,acc[0][0]); acc[0][1]=ffma2(a0,b0.y,acc[0][1]);
            acc[0][2]=ffma2(a0,b1.x,acc[0][2]); acc[0][3]=ffma2(a0,b1.y,acc[0][3]);
            acc[1][0]=ffma2(a1,b0.x,acc[1][0]); acc[1][1]=ffma2(a1,b0.y,acc[1][1]);
            acc[1][2]=ffma2(a1,b1.x,acc[1][2]); acc[1][3]=ffma2(a1,b1.y,acc[1][3]);
            acc[2][0]=ffma2(a2,b0.x,acc[2][0]); acc[2][1]=ffma2(a2,b0.y,acc[2][1]);
            acc[2][2]=ffma2(a2,b1.x,acc[2][2]); acc[2][3]=ffma2(a2,b1.y,acc[2][3]);
            acc[3][0]=ffma2(a3,b0.x,acc[3][0]); acc[3][1]=ffma2(a3,b0.y,acc[3][1]);
            acc[3][2]=ffma2(a3,b1.x,acc[3][2]); acc[3][3]=ffma2(a3,b1.y,acc[3][3]);
        }
        __syncthreads();
    }
    long pb = (long)blockIdx.x * 8192;
    #pragma unroll
    for (int a = 0; a < 4; a++)
        #pragma unroll
        for (int p = 0; p < 4; p++) {
            float lo, hi;
            asm("mov.b64 {%0, %1}, %2;" : "=f"(lo), "=f"(hi) : "l"(acc[a][p]));
            int m = ty*4 + a, n = tx*8 + p*2;
            d_part[pb + m*128 + n]     = lo;
            d_part[pb + m*128 + n + 1] = hi;
        }
}

// ------------- reduce partials + bias, split (mu, logvar) -------------
__global__ void k_fin(const float* __restrict__ bfc, float* __restrict__ out) {
    int e = blockIdx.x * blockDim.x + threadIdx.x;
    if (e >= 8192) return;
    float s0 = 0.f, s1 = 0.f, s2 = 0.f, s3 = 0.f;
    for (int blk = 0; blk < NKB; blk += 4) {
        s0 += d_part[(long)(blk+0)*8192 + e];
        s1 += d_part[(long)(blk+1)*8192 + e];
        s2 += d_part[(long)(blk+2)*8192 + e];
        s3 += d_part[(long)(blk+3)*8192 + e];
    }
    int b = e >> 7, j = e & 127;
    float v = (s0 + s1) + (s2 + s3) + bfc[j];
    out[(j >> 6) * 4096 + b*64 + (j & 63)] = v;   // mu block then logvar block
}

extern "C" void kernel_launch(void* const* d_in, const int* in_sizes, int n_in,
                              void* d_out, int out_size) {
    const float* x0    = (const float*)d_in[0];
    const float* x1    = (const float*)d_in[1];
    const float* x2    = (const float*)d_in[2];
    const float* x3    = (const float*)d_in[3];
    const float* x4    = (const float*)d_in[4];
    const float* Wlin  = (const float*)d_in[5];
    const float* bias0 = (const float*)d_in[6];
    const float* w3j   = (const float*)d_in[7];
    const float* Wfc   = (const float*)d_in[8];
    const float* bfc   = (const float*)d_in[9];
    float* out = (float*)d_out;

    k_setup<<<1, 256>>>();
    k_y<<<64, 256>>>(x0, x1, x2, x3, x4, Wlin, bias0);

    // triple counts per l3: {5,8,10,10,9,6,4,2,1}, cumulative offsets below
    k_trip<1> <<<dim3(5, 64),  256>>>(w3j, 0);
    k_trip<3> <<<dim3(8, 64),  256>>>(w3j, 5);
    k_trip<5> <<<dim3(10, 64), 256>>>(w3j, 13);
    k_trip<7> <<<dim3(10, 64), 256>>>(w3j, 23);
    k_trip<9> <<<dim3(9, 64),  256>>>(w3j, 33);
    k_trip<11><<<dim3(6, 64),  256>>>(w3j, 42);
    k_trip<13><<<dim3(4, 64),  256>>>(w3j, 48);
    k_trip<15><<<dim3(2, 64),  256>>>(w3j, 52);
    k_trip<17><<<dim3(1, 64),  256>>>(w3j, 54);

    k_scal<<<1, 64>>>();
    k_bn<<<NTRIP * 32, 256>>>();
    k_gemm<<<NKB, 256>>>(Wfc);
    k_fin<<<32, 256>>>(bfc, out);
}

// round 7
// speedup vs baseline: 1.1321x; 1.1321x over previous
#include <cuda_runtime.h>

#define NTRIP 55
#define DTOT  404480
#define EPSV  1e-6f
#define NKB   1580
#define KSPAN 256

__device__ int   d_l1[NTRIP], d_l2[NTRIP], d_l3a[NTRIP], d_widx[NTRIP], d_based[NTRIP];
__device__ int   d_cnt[9];
__device__ float d_sumsq[64 * 9];
__device__ float d_sum0[64];
__device__ float d_A[64 * 9];
__device__ float d_D0[64];
__device__ float d_y[64 * 800];          // per-b: l-offsets 0,32,128,288,512
__device__ float d_z[64LL * DTOT];
__device__ float d_g[DTOT];              // BN gain per d
__device__ float d_m[5120];              // BN mean per d (l3=0 region only)
__device__ float d_part[(long)NKB * 8192];

// ------------- y = Wlin@x (+bias0); block 0 also builds tables + zeros stats -------------
__global__ void k_y(const float* __restrict__ x0, const float* __restrict__ x1,
                    const float* __restrict__ x2, const float* __restrict__ x3,
                    const float* __restrict__ x4, const float* __restrict__ Wlin,
                    const float* __restrict__ bias0) {
    int b = blockIdx.x, t = threadIdx.x;
    if (b == 0) {
        if (t == 0) {
            int L1[NTRIP], L2[NTRIP], L3[NTRIP], n = 0;
            for (int l1 = 0; l1 <= 4; l1++)
                for (int l2 = l1; l2 <= 4; l2++)
                    for (int l3 = l2 - l1; l3 <= l1 + l2; l3++) { L1[n]=l1; L2[n]=l2; L3[n]=l3; n++; }
            int idx = 0, based = 0;
            for (int lv = 0; lv <= 8; lv++) {
                int c = 0;
                for (int s = 0; s < n; s++) if (L3[s] == lv) {
                    d_l1[idx]=L1[s]; d_l2[idx]=L2[s]; d_l3a[idx]=lv; d_widx[idx]=s; d_based[idx]=based;
                    based += 1024 * (2*lv + 1); idx++; c++;
                }
                d_cnt[lv] = c * 1024 * (2*lv + 1);
            }
        }
        for (int i = t; i < 64*9; i += blockDim.x) d_sumsq[i] = 0.f;
        for (int i = t; i < 64;   i += blockDim.x) d_sum0[i]  = 0.f;
    }
    const float* xs[5] = {x0, x1, x2, x3, x4};
    const int yo[5] = {0, 32, 128, 288, 512};
    for (int l = 0; l < 5; l++) {
        int M = 2*l + 1;
        const float* x = xs[l] + (long)b * 32 * M;
        for (int e = t; e < 32 * M; e += blockDim.x) {
            int o = e / M, m = e % M;
            float acc = (l == 0) ? bias0[o] : 0.f;
            const float* wr = Wlin + (l*32 + o) * 32;
            #pragma unroll 8
            for (int i = 0; i < 32; i++) acc += wr[i] * x[i*M + m];
            d_y[b*800 + yo[l] + o*M + m] = acc;
        }
    }
}

// ------------- triple products + row-norm + LN stats (single launch, template dispatch) -------------
template <int K3>
__device__ __forceinline__ void trip_body(int tr, int b, const float* __restrict__ w3j,
                                          float* sy1, float* sy2, float* sw, float* su,
                                          float* r1, float* r2) {
    const int l3v = (K3 - 1) / 2;
    const int l1 = d_l1[tr], l2 = d_l2[tr];
    const int m1 = 2*l1 + 1, n2 = 2*l2 + 1;
    const int yo[5] = {0, 32, 128, 288, 512};
    int t = threadIdx.x;

    for (int e = t; e < 32*m1; e += 256) sy1[e] = d_y[b*800 + yo[l1] + e];
    for (int e = t; e < 32*n2; e += 256) sy2[e] = d_y[b*800 + yo[l2] + e];
    const float* wp = w3j + (long)d_widx[tr] * 9 * 9 * 17;
    for (int e = t; e < m1*n2*K3; e += 256) {
        int m = e / (n2*K3), r = e % (n2*K3), nn = r / K3, k = r % K3;
        sw[e] = wp[m*153 + nn*17 + k];
    }
    __syncthreads();
    // u[j,m,k] = sum_n y2[j,n] * w[m,n,k]
    for (int e = t; e < 32*m1*K3; e += 256) {
        int j = e / (m1*K3), r = e % (m1*K3), m = r / K3, k = r % K3;
        float a = 0.f;
        for (int nn = 0; nn < n2; nn++) a += sy2[j*n2 + nn] * sw[(m*n2 + nn)*K3 + k];
        su[e] = a;
    }
    __syncthreads();

    float lsq = 0.f, ls0 = 0.f;
    long zbase = (long)b * DTOT + d_based[tr];
    for (int p = t; p < 1024; p += 256) {
        int i = p >> 5, j = p & 31;
        float acc[K3];
        #pragma unroll
        for (int k = 0; k < K3; k++) acc[k] = 0.f;
        const float* y1p = &sy1[i*m1];
        for (int m = 0; m < m1; m++) {
            float ym = y1p[m];
            const float* up = &su[(j*m1 + m)*K3];
            #pragma unroll
            for (int k = 0; k < K3; k++) acc[k] += ym * up[k];
        }
        float S = 0.f;
        #pragma unroll
        for (int k = 0; k < K3; k++) S += acc[k]*acc[k];
        float inv = rsqrtf(S + EPSV);
        float* zp = &d_z[zbase + (long)p * K3];
        #pragma unroll
        for (int k = 0; k < K3; k++) zp[k] = acc[k] * inv;
        lsq += S * inv * inv;
        if (K3 == 1) ls0 += acc[0] * inv;
    }
    r1[t] = lsq; r2[t] = ls0;
    __syncthreads();
    for (int s = 128; s > 0; s >>= 1) {
        if (t < s) { r1[t] += r1[t+s]; r2[t] += r2[t+s]; }
        __syncthreads();
    }
    if (t == 0) {
        atomicAdd(&d_sumsq[b*9 + l3v], r1[0]);
        if (K3 == 1) atomicAdd(&d_sum0[b], r2[0]);
    }
}

__global__ void __launch_bounds__(256) k_trip_all(const float* __restrict__ w3j) {
    __shared__ float sy1[288], sy2[288], sw[1377], su[4896], r1[256], r2[256];
    int tr = blockIdx.x, b = blockIdx.y;
    switch (d_l3a[tr]) {
        case 0: trip_body<1> (tr, b, w3j, sy1, sy2, sw, su, r1, r2); break;
        case 1: trip_body<3> (tr, b, w3j, sy1, sy2, sw, su, r1, r2); break;
        case 2: trip_body<5> (tr, b, w3j, sy1, sy2, sw, su, r1, r2); break;
        case 3: trip_body<7> (tr, b, w3j, sy1, sy2, sw, su, r1, r2); break;
        case 4: trip_body<9> (tr, b, w3j, sy1, sy2, sw, su, r1, r2); break;
        case 5: trip_body<11>(tr, b, w3j, sy1, sy2, sw, su, r1, r2); break;
        case 6: trip_body<13>(tr, b, w3j, sy1, sy2, sw, su, r1, r2); break;
        case 7: trip_body<15>(tr, b, w3j, sy1, sy2, sw, su, r1, r2); break;
        case 8: trip_body<17>(tr, b, w3j, sy1, sy2, sw, su, r1, r2); break;
    }
}

// ------------- per-(b,l3) scalars: power-scale + LN folded into affine A,D -------------
__global__ void k_scal() {
    int b = threadIdx.x;
    if (b >= 64) return;
    float power = 0.f;
    for (int l = 0; l < 9; l++) power += d_sumsq[b*9 + l];
    float scale = rsqrtf(power / (float)DTOT + EPSV);
    for (int l = 0; l < 9; l++) {
        float ms = scale * scale * d_sumsq[b*9 + l] / (float)d_cnt[l];
        if (l == 0) {
            float mu  = scale * d_sum0[b] / (float)d_cnt[0];
            float c   = rsqrtf(ms - mu*mu + EPSV);
            d_A[b*9]  = scale * c;
            d_D0[b]   = -mu * c;
        } else {
            d_A[b*9 + l] = scale * rsqrtf(ms + EPSV);
        }
    }
}

// ------------- BN stats only (read z once; write per-d gain g and mean m) -------------
__global__ void __launch_bounds__(256) k_bnstat() {
    int tr = blockIdx.x >> 5, i = blockIdx.x & 31;
    int l3v = d_l3a[tr], k3 = 2*l3v + 1, E = 32 * k3;
    long base = (long)d_based[tr] + (long)i * E;
    __shared__ float sA[64], sD[64], ssq[544], ssum[544], sg[32], sm2[32];
    int t = threadIdx.x;
    if (t < 64) { sA[t] = d_A[t*9 + l3v]; sD[t] = (l3v == 0) ? d_D0[t] : 0.f; }
    __syncthreads();
    for (int e = t; e < E; e += 256) {
        float asq = 0.f, asum = 0.f;
        for (int b = 0; b < 64; b++) {
            float v = sA[b] * d_z[(long)b*DTOT + base + e] + sD[b];
            asq += v*v; asum += v;
        }
        ssq[e] = asq; ssum[e] = asum;
    }
    __syncthreads();
    if (t < 32) {
        float sq = 0.f, sm = 0.f;
        for (int k = 0; k < k3; k++) { sq += ssq[t*k3 + k]; sm += ssum[t*k3 + k]; }
        if (l3v == 0) {
            float m = sm * (1.f/64.f);
            sg[t] = rsqrtf(sq*(1.f/64.f) - m*m + EPSV); sm2[t] = m;
        } else {
            sg[t] = rsqrtf(sq / (64.f * (float)k3) + EPSV); sm2[t] = 0.f;
        }
    }
    __syncthreads();
    for (int e = t; e < E; e += 256) {
        int j = e / k3;
        d_g[base + e] = sg[j];
        if (l3v == 0) d_m[base + e] = sm2[j];
    }
}

// ------------- split-K GEMM with fused BN affine on the A-tile load -------------
__device__ __forceinline__ unsigned long long pk2(float x, float y) {
    unsigned long long r;
    asm("mov.b64 %0, {%1, %2};" : "=l"(r) : "f"(x), "f"(y));
    return r;
}
__device__ __forceinline__ unsigned long long ffma2(unsigned long long a, unsigned long long b,
                                                    unsigned long long c) {
    unsigned long long d;
    asm("fma.rn.f32x2 %0, %1, %2, %3;" : "=l"(d) : "l"(a), "l"(b), "l"(c));
    return d;
}

__global__ void __launch_bounds__(256) k_gemm(const float* __restrict__ W) {
    __shared__ __align__(16) float As[32][68];
    __shared__ __align__(16) float Bs[32][132];
    __shared__ float sA[64], sDv[64];
    int t = threadIdx.x, ty = t >> 4, tx = t & 15;
    long kbase = (long)blockIdx.x * KSPAN;

    // l3 region of this K-block (block never straddles a boundary: KSPAN | 1024 | region sizes)
    int l3v;
    if      (kbase < 5120)   l3v = 0;
    else if (kbase < 29696)  l3v = 1;
    else if (kbase < 80896)  l3v = 2;
    else if (kbase < 152576) l3v = 3;
    else if (kbase < 235520) l3v = 4;
    else if (kbase < 303104) l3v = 5;
    else if (kbase < 356352) l3v = 6;
    else if (kbase < 387072) l3v = 7;
    else                     l3v = 8;
    bool hasm = (l3v == 0);

    if (t < 64) { sA[t] = d_A[t*9 + l3v]; sDv[t] = hasm ? d_D0[t] : 0.f; }
    __syncthreads();

    unsigned long long acc[4][4];
    #pragma unroll
    for (int a = 0; a < 4; a++)
        #pragma unroll
        for (int p = 0; p < 4; p++) acc[a][p] = 0ULL;

    for (int c = 0; c < KSPAN/32; c++) {
        long kg = kbase + c*32;
        #pragma unroll
        for (int r = 0; r < 8; r++) {
            int q = t + r*256, row = q >> 5, kk = q & 31;
            float z = d_z[(long)row*DTOT + kg + kk];
            float g = __ldg(&d_g[kg + kk]);
            float mm = hasm ? __ldg(&d_m[kg + kk]) : 0.f;
            As[kk][row] = g * (sA[row]*z + sDv[row] - mm);
        }
        #pragma unroll
        for (int r = 0; r < 16; r++) {
            int q = t + r*256, row = q >> 5, kk = q & 31;
            Bs[kk][row] = W[(long)row*DTOT + kg + kk];
        }
        __syncthreads();
        #pragma unroll 8
        for (int k = 0; k < 32; k++) {
            float4 av = *(const float4*)&As[k][ty*4];
            ulonglong2 b0 = *(const ulonglong2*)&Bs[k][tx*8];
            ulonglong2 b1 = *(const ulonglong2*)&Bs[k][tx*8 + 4];
            unsigned long long a0 = pk2(av.x, av.x), a1 = pk2(av.y, av.y);
            unsigned long long a2 = pk2(av.z, av.z), a3 = pk2(av.w, av.w);
            acc[0][0]=ffma2(a0,b0.x,acc[0][0]); acc[0][1]=ffma2(a0,b0.y,acc[0][1]);
            acc[0][2]=ffma2(a0,b1.x,acc[0][2]); acc[0][3]=ffma2(a0,b1.y,acc[0][3]);
            acc[1][0]=ffma2(a1,b0.x,acc[1][0]); acc[1][1]=ffma2(a1,b0.y,acc[1][1]);
            acc[1][2]=ffma2(a1,b1.x,acc[1][2]); acc[1][3]=ffma2(a1,b1.y,acc[1][3]);
            acc[2][0]=ffma2(a2,b0.x,acc[2][0]); acc[2][1]=ffma2(a2,b0.y,acc[2][1]);
            acc[2][2]=ffma2(a2,b1.x,acc[2][2]); acc[2][3]=ffma2(a2,b1.y,acc[2][3]);
            acc[3][0]=ffma2(a3,b0.x,acc[3][0]); acc[3][1]=ffma2(a3,b0.y,acc[3][1]);
            acc[3][2]=ffma2(a3,b1.x,acc[3][2]); acc[3][3]=ffma2(a3,b1.y,acc[3][3]);
        }
        __syncthreads();
    }
    long pb = (long)blockIdx.x * 8192;
    #pragma unroll
    for (int a = 0; a < 4; a++)
        #pragma unroll
        for (int p = 0; p < 4; p++) {
            float lo, hi;
            asm("mov.b64 {%0, %1}, %2;" : "=f"(lo), "=f"(hi) : "l"(acc[a][p]));
            int m = ty*4 + a, n = tx*8 + p*2;
            d_part[pb + m*128 + n]     = lo;
            d_part[pb + m*128 + n + 1] = hi;
        }
}

// ------------- reduce partials + bias, split (mu, logvar) -------------
__global__ void k_fin(const float* __restrict__ bfc, float* __restrict__ out) {
    int e = blockIdx.x * blockDim.x + threadIdx.x;
    if (e >= 8192) return;
    float s0 = 0.f, s1 = 0.f, s2 = 0.f, s3 = 0.f;
    for (int blk = 0; blk < NKB; blk += 4) {
        s0 += d_part[(long)(blk+0)*8192 + e];
        s1 += d_part[(long)(blk+1)*8192 + e];
        s2 += d_part[(long)(blk+2)*8192 + e];
        s3 += d_part[(long)(blk+3)*8192 + e];
    }
    int b = e >> 7, j = e & 127;
    float v = (s0 + s1) + (s2 + s3) + bfc[j];
    out[(j >> 6) * 4096 + b*64 + (j & 63)] = v;   // mu block then logvar block
}

extern "C" void kernel_launch(void* const* d_in, const int* in_sizes, int n_in,
                              void* d_out, int out_size) {
    const float* x0    = (const float*)d_in[0];
    const float* x1    = (const float*)d_in[1];
    const float* x2    = (const float*)d_in[2];
    const float* x3    = (const float*)d_in[3];
    const float* x4    = (const float*)d_in[4];
    const float* Wlin  = (const float*)d_in[5];
    const float* bias0 = (const float*)d_in[6];
    const float* w3j   = (const float*)d_in[7];
    const float* Wfc   = (const float*)d_in[8];
    const float* bfc   = (const float*)d_in[9];
    float* out = (float*)d_out;

    k_y<<<64, 256>>>(x0, x1, x2, x3, x4, Wlin, bias0);
    k_trip_all<<<dim3(NTRIP, 64), 256>>>(w3j);
    k_scal<<<1, 64>>>();
    k_bnstat<<<NTRIP * 32, 256>>>();
    k_gemm<<<NKB, 256>>>(Wfc);
    k_fin<<<32, 256>>>(bfc, out);
}

// round 11
// speedup vs baseline: 1.9736x; 1.7433x over previous
#include <cuda_runtime.h>
#include <cstdint>

#define NTRIP 55
#define DTOT  404480
#define EPSV  1e-6f
#define NKB   395
#define KSPAN 1024
#define NCH   32          // chunks of 32 f32 per CTA

__device__ int   d_l1[NTRIP], d_l2[NTRIP], d_l3a[NTRIP], d_widx[NTRIP], d_based[NTRIP];
__device__ int   d_cnt[9];
__device__ float d_sumsq[64 * 9];
__device__ float d_sum0[64];
__device__ float d_A[64 * 9];
__device__ float d_D0[64];
__device__ float d_y[64 * 800];
__device__ float d_z[64LL * DTOT];
__device__ float d_g[DTOT];
__device__ float d_m[5120];
__device__ float d_part[(long)NKB * 8192];

__device__ __forceinline__ float tf32r(float x) {
    asm("cvt.rna.tf32.f32 %0, %0;" : "+f"(x));
    return x;
}

// ------------- y = Wlin@x (+bias0); block 0 builds tables + zeros stats -------------
__global__ void k_y(const float* __restrict__ x0, const float* __restrict__ x1,
                    const float* __restrict__ x2, const float* __restrict__ x3,
                    const float* __restrict__ x4, const float* __restrict__ Wlin,
                    const float* __restrict__ bias0) {
    int b = blockIdx.x, t = threadIdx.x;
    if (b == 0) {
        if (t == 0) {
            int L1[NTRIP], L2[NTRIP], L3[NTRIP], n = 0;
            for (int l1 = 0; l1 <= 4; l1++)
                for (int l2 = l1; l2 <= 4; l2++)
                    for (int l3 = l2 - l1; l3 <= l1 + l2; l3++) { L1[n]=l1; L2[n]=l2; L3[n]=l3; n++; }
            int idx = 0, based = 0;
            for (int lv = 0; lv <= 8; lv++) {
                int c = 0;
                for (int s = 0; s < n; s++) if (L3[s] == lv) {
                    d_l1[idx]=L1[s]; d_l2[idx]=L2[s]; d_l3a[idx]=lv; d_widx[idx]=s; d_based[idx]=based;
                    based += 1024 * (2*lv + 1); idx++; c++;
                }
                d_cnt[lv] = c * 1024 * (2*lv + 1);
            }
        }
        for (int i = t; i < 64*9; i += blockDim.x) d_sumsq[i] = 0.f;
        for (int i = t; i < 64;   i += blockDim.x) d_sum0[i]  = 0.f;
    }
    const float* xs[5] = {x0, x1, x2, x3, x4};
    const int yo[5] = {0, 32, 128, 288, 512};
    for (int l = 0; l < 5; l++) {
        int M = 2*l + 1;
        const float* x = xs[l] + (long)b * 32 * M;
        for (int e = t; e < 32 * M; e += blockDim.x) {
            int o = e / M, m = e % M;
            float acc = (l == 0) ? bias0[o] : 0.f;
            const float* wr = Wlin + (l*32 + o) * 32;
            #pragma unroll 8
            for (int i = 0; i < 32; i++) acc += wr[i] * x[i*M + m];
            d_y[b*800 + yo[l] + o*M + m] = acc;
        }
    }
}

// ------------- triple products + row-norm + LN stats (single launch) -------------
template <int K3>
__device__ __forceinline__ void trip_body(int tr, int b, const float* __restrict__ w3j,
                                          float* sy1, float* sy2, float* sw, float* su,
                                          float* r1, float* r2) {
    const int l3v = (K3 - 1) / 2;
    const int l1 = d_l1[tr], l2 = d_l2[tr];
    const int m1 = 2*l1 + 1, n2 = 2*l2 + 1;
    const int yo[5] = {0, 32, 128, 288, 512};
    int t = threadIdx.x;

    for (int e = t; e < 32*m1; e += 256) sy1[e] = d_y[b*800 + yo[l1] + e];
    for (int e = t; e < 32*n2; e += 256) sy2[e] = d_y[b*800 + yo[l2] + e];
    const float* wp = w3j + (long)d_widx[tr] * 9 * 9 * 17;
    for (int e = t; e < m1*n2*K3; e += 256) {
        int m = e / (n2*K3), r = e % (n2*K3), nn = r / K3, k = r % K3;
        sw[e] = wp[m*153 + nn*17 + k];
    }
    __syncthreads();
    for (int e = t; e < 32*m1*K3; e += 256) {
        int j = e / (m1*K3), r = e % (m1*K3), m = r / K3, k = r % K3;
        float a = 0.f;
        for (int nn = 0; nn < n2; nn++) a += sy2[j*n2 + nn] * sw[(m*n2 + nn)*K3 + k];
        su[e] = a;
    }
    __syncthreads();

    float lsq = 0.f, ls0 = 0.f;
    long zbase = (long)b * DTOT + d_based[tr];
    for (int p = t; p < 1024; p += 256) {
        int i = p >> 5, j = p & 31;
        float acc[K3];
        #pragma unroll
        for (int k = 0; k < K3; k++) acc[k] = 0.f;
        const float* y1p = &sy1[i*m1];
        for (int m = 0; m < m1; m++) {
            float ym = y1p[m];
            const float* up = &su[(j*m1 + m)*K3];
            #pragma unroll
            for (int k = 0; k < K3; k++) acc[k] += ym * up[k];
        }
        float S = 0.f;
        #pragma unroll
        for (int k = 0; k < K3; k++) S += acc[k]*acc[k];
        float inv = rsqrtf(S + EPSV);
        float* zp = &d_z[zbase + (long)p * K3];
        #pragma unroll
        for (int k = 0; k < K3; k++) zp[k] = acc[k] * inv;
        lsq += S * inv * inv;
        if (K3 == 1) ls0 += acc[0] * inv;
    }
    r1[t] = lsq; r2[t] = ls0;
    __syncthreads();
    for (int s = 128; s > 0; s >>= 1) {
        if (t < s) { r1[t] += r1[t+s]; r2[t] += r2[t+s]; }
        __syncthreads();
    }
    if (t == 0) {
        atomicAdd(&d_sumsq[b*9 + l3v], r1[0]);
        if (K3 == 1) atomicAdd(&d_sum0[b], r2[0]);
    }
}

__global__ void __launch_bounds__(256) k_trip_all(const float* __restrict__ w3j) {
    __shared__ float sy1[288], sy2[288], sw[1377], su[4896], r1[256], r2[256];
    int tr = blockIdx.x, b = blockIdx.y;
    switch (d_l3a[tr]) {
        case 0: trip_body<1> (tr, b, w3j, sy1, sy2, sw, su, r1, r2); break;
        case 1: trip_body<3> (tr, b, w3j, sy1, sy2, sw, su, r1, r2); break;
        case 2: trip_body<5> (tr, b, w3j, sy1, sy2, sw, su, r1, r2); break;
        case 3: trip_body<7> (tr, b, w3j, sy1, sy2, sw, su, r1, r2); break;
        case 4: trip_body<9> (tr, b, w3j, sy1, sy2, sw, su, r1, r2); break;
        case 5: trip_body<11>(tr, b, w3j, sy1, sy2, sw, su, r1, r2); break;
        case 6: trip_body<13>(tr, b, w3j, sy1, sy2, sw, su, r1, r2); break;
        case 7: trip_body<15>(tr, b, w3j, sy1, sy2, sw, su, r1, r2); break;
        case 8: trip_body<17>(tr, b, w3j, sy1, sy2, sw, su, r1, r2); break;
    }
}

// ------------- per-(b,l3) scalars -------------
__global__ void k_scal() {
    int b = threadIdx.x;
    if (b >= 64) return;
    float power = 0.f;
    for (int l = 0; l < 9; l++) power += d_sumsq[b*9 + l];
    float scale = rsqrtf(power / (float)DTOT + EPSV);
    for (int l = 0; l < 9; l++) {
        float ms = scale * scale * d_sumsq[b*9 + l] / (float)d_cnt[l];
        if (l == 0) {
            float mu  = scale * d_sum0[b] / (float)d_cnt[0];
            float c   = rsqrtf(ms - mu*mu + EPSV);
            d_A[b*9]  = scale * c;
            d_D0[b]   = -mu * c;
        } else {
            d_A[b*9 + l] = scale * rsqrtf(ms + EPSV);
        }
    }
}

// ------------- BN stats (float4 loads, 4x MLP) -------------
__global__ void __launch_bounds__(128) k_bnstat() {
    int tr = blockIdx.x >> 5, i = blockIdx.x & 31;
    int l3v = d_l3a[tr], k3 = 2*l3v + 1, E = 32 * k3;
    long base = (long)d_based[tr] + (long)i * E;
    __shared__ float sA[64], sD[64], ssq[544], ssum[544], sg[32], sm2[32];
    int t = threadIdx.x;
    if (t < 64) { sA[t] = d_A[t*9 + l3v]; sD[t] = (l3v == 0) ? d_D0[t] : 0.f; }
    __syncthreads();
    int nf4 = E >> 2;
    for (int f = t; f < nf4; f += 128) {
        float qx=0,qy=0,qz=0,qw=0, sx=0,sy=0,sz=0,sw2=0;
        #pragma unroll 4
        for (int b = 0; b < 64; b++) {
            float4 z4 = *(const float4*)&d_z[(long)b*DTOT + base + f*4];
            float a = sA[b], dd = sD[b];
            float vx = a*z4.x+dd, vy = a*z4.y+dd, vz = a*z4.z+dd, vw = a*z4.w+dd;
            qx += vx*vx; qy += vy*vy; qz += vz*vz; qw += vw*vw;
            sx += vx; sy += vy; sz += vz; sw2 += vw;
        }
        ssq[f*4]=qx; ssq[f*4+1]=qy; ssq[f*4+2]=qz; ssq[f*4+3]=qw;
        ssum[f*4]=sx; ssum[f*4+1]=sy; ssum[f*4+2]=sz; ssum[f*4+3]=sw2;
    }
    __syncthreads();
    if (t < 32) {
        float sq = 0.f, sm = 0.f;
        for (int k = 0; k < k3; k++) { sq += ssq[t*k3 + k]; sm += ssum[t*k3 + k]; }
        if (l3v == 0) {
            float m = sm * (1.f/64.f);
            sg[t] = rsqrtf(sq*(1.f/64.f) - m*m + EPSV); sm2[t] = m;
        } else {
            sg[t] = rsqrtf(sq / (64.f * (float)k3) + EPSV); sm2[t] = 0.f;
        }
    }
    __syncthreads();
    for (int e = t; e < E; e += 128) {
        int j = e / k3;
        d_g[base + e] = sg[j];
        if (l3v == 0) d_m[base + e] = sm2[j];
    }
}

// ------------- split-K GEMM via mma.sync tf32 (sm_80+ PTX, no 'a' features) -------------
// C[j=0..127][b=0..63] = sum_k W[j,k] * z'[b,k];  z' = g*(A_b*z + D_b - m) fused on load.
__global__ void __launch_bounds__(256, 2) k_gemm_mma(const float* __restrict__ W) {
    __shared__ float As[128][36];   // W rows x k (pad 36: frag bank = 4*gid+tid4, conflict-free)
    __shared__ float Bs[64][36];    // batch rows x k
    __shared__ float sA[64], sD[64];
    int t = threadIdx.x;
    int w = t >> 5, lane = t & 31, gid = lane >> 2, tid4 = lane & 3;
    long kbase = (long)blockIdx.x * KSPAN;

    int l3v;
    if      (kbase < 5120)   l3v = 0;
    else if (kbase < 29696)  l3v = 1;
    else if (kbase < 80896)  l3v = 2;
    else if (kbase < 152576) l3v = 3;
    else if (kbase < 235520) l3v = 4;
    else if (kbase < 303104) l3v = 5;
    else if (kbase < 356352) l3v = 6;
    else if (kbase < 387072) l3v = 7;
    else                     l3v = 8;
    bool hasm = (l3v == 0);

    if (t < 64) { sA[t] = d_A[t*9 + l3v]; sD[t] = hasm ? d_D0[t] : 0.f; }
    __syncthreads();

    float c[8][4];
    #pragma unroll
    for (int nt = 0; nt < 8; nt++)
        #pragma unroll
        for (int q = 0; q < 4; q++) c[nt][q] = 0.f;

    float4 av[4], bv[2], gv[2], mv[2];
    // prefetch chunk 0
    {
        long kg = kbase;
        #pragma unroll
        for (int i = 0; i < 4; i++) {
            int id = t + i*256, r = id >> 3, cc = (id & 7) * 4;
            av[i] = *(const float4*)(W + (long)r*DTOT + kg + cc);
        }
        #pragma unroll
        for (int i = 0; i < 2; i++) {
            int id = t + i*256, r = id >> 3, cc = (id & 7) * 4;
            bv[i] = *(const float4*)(d_z + (long)r*DTOT + kg + cc);
            gv[i] = *(const float4*)(d_g + kg + cc);
            mv[i] = hasm ? *(const float4*)(d_m + kg + cc) : make_float4(0.f,0.f,0.f,0.f);
        }
    }

    for (int ch = 0; ch < NCH; ch++) {
        // stage regs -> smem (with BN affine + tf32 rounding)
        #pragma unroll
        for (int i = 0; i < 4; i++) {
            int id = t + i*256, r = id >> 3, cc = (id & 7) * 4;
            float4 v = av[i];
            v.x = tf32r(v.x); v.y = tf32r(v.y); v.z = tf32r(v.z); v.w = tf32r(v.w);
            *(float4*)&As[r][cc] = v;
        }
        #pragma unroll
        for (int i = 0; i < 2; i++) {
            int id = t + i*256, r = id >> 3, cc = (id & 7) * 4;
            float a = sA[r], dd = sD[r];
            float4 v;
            v.x = tf32r(gv[i].x * (a*bv[i].x + dd - mv[i].x));
            v.y = tf32r(gv[i].y * (a*bv[i].y + dd - mv[i].y));
            v.z = tf32r(gv[i].z * (a*bv[i].z + dd - mv[i].z));
            v.w = tf32r(gv[i].w * (a*bv[i].w + dd - mv[i].w));
            *(float4*)&Bs[r][cc] = v;
        }
        __syncthreads();
        // prefetch next chunk (overlaps mma below)
        if (ch + 1 < NCH) {
            long kg = kbase + (ch + 1) * 32;
            #pragma unroll
            for (int i = 0; i < 4; i++) {
                int id = t + i*256, r = id >> 3, cc = (id & 7) * 4;
                av[i] = *(const float4*)(W + (long)r*DTOT + kg + cc);
            }
            #pragma unroll
            for (int i = 0; i < 2; i++) {
                int id = t + i*256, r = id >> 3, cc = (id & 7) * 4;
                bv[i] = *(const float4*)(d_z + (long)r*DTOT + kg + cc);
                gv[i] = *(const float4*)(d_g + kg + cc);
                mv[i] = hasm ? *(const float4*)(d_m + kg + cc) : make_float4(0.f,0.f,0.f,0.f);
            }
        }
        // compute: 4 k-steps x 8 n-tiles of m16n8k8
        #pragma unroll
        for (int ks = 0; ks < 4; ks++) {
            int k0 = ks * 8;
            int ar = w*16 + gid;
            unsigned a0 = __float_as_uint(As[ar][k0 + tid4]);
            unsigned a1 = __float_as_uint(As[ar + 8][k0 + tid4]);
            unsigned a2 = __float_as_uint(As[ar][k0 + tid4 + 4]);
            unsigned a3 = __float_as_uint(As[ar + 8][k0 + tid4 + 4]);
            #pragma unroll
            for (int nt = 0; nt < 8; nt++) {
                unsigned b0 = __float_as_uint(Bs[nt*8 + gid][k0 + tid4]);
                unsigned b1 = __float_as_uint(Bs[nt*8 + gid][k0 + tid4 + 4]);
                asm volatile(
                    "mma.sync.aligned.m16n8k8.row.col.f32.tf32.tf32.f32 "
                    "{%0,%1,%2,%3}, {%4,%5,%6,%7}, {%8,%9}, {%0,%1,%2,%3};"
                    : "+f"(c[nt][0]), "+f"(c[nt][1]), "+f"(c[nt][2]), "+f"(c[nt][3])
                    : "r"(a0), "r"(a1), "r"(a2), "r"(a3), "r"(b0), "r"(b1));
            }
        }
        __syncthreads();
    }

    // epilogue: part[blk][j][b], j = W row (feature), b = batch
    long pb = (long)blockIdx.x * 8192;
    int j0 = w*16 + gid, n0 = tid4 * 2;
    #pragma unroll
    for (int nt = 0; nt < 8; nt++) {
        int n = nt*8 + n0;
        *(float2*)&d_part[pb + (long)j0*64 + n]       = make_float2(c[nt][0], c[nt][1]);
        *(float2*)&d_part[pb + (long)(j0 + 8)*64 + n] = make_float2(c[nt][2], c[nt][3]);
    }
}

// ------------- reduce partials + bias, split (mu, logvar) -------------
__global__ void k_fin(const float* __restrict__ bfc, float* __restrict__ out) {
    int e = blockIdx.x * blockDim.x + threadIdx.x;
    if (e >= 8192) return;
    float s = 0.f;
    #pragma unroll 5
    for (int blk = 0; blk < NKB; blk++) s += d_part[(long)blk * 8192 + e];
    int j = e >> 6, b = e & 63;
    out[(j >> 6) * 4096 + b*64 + (j & 63)] = s + bfc[j];
}

extern "C" void kernel_launch(void* const* d_in, const int* in_sizes, int n_in,
                              void* d_out, int out_size) {
    const float* x0    = (const float*)d_in[0];
    const float* x1    = (const float*)d_in[1];
    const float* x2    = (const float*)d_in[2];
    const float* x3    = (const float*)d_in[3];
    const float* x4    = (const float*)d_in[4];
    const float* Wlin  = (const float*)d_in[5];
    const float* bias0 = (const float*)d_in[6];
    const float* w3j   = (const float*)d_in[7];
    const float* Wfc   = (const float*)d_in[8];
    const float* bfc   = (const float*)d_in[9];
    float* out = (float*)d_out;

    k_y<<<64, 256>>>(x0, x1, x2, x3, x4, Wlin, bias0);
    k_trip_all<<<dim3(NTRIP, 64), 256>>>(w3j);
    k_scal<<<1, 64>>>();
    k_bnstat<<<NTRIP * 32, 128>>>();
    k_gemm_mma<<<NKB, 256>>>(Wfc);
    k_fin<<<32, 256>>>(bfc, out);
}

// round 12
// speedup vs baseline: 2.1401x; 1.0844x over previous
#include <cuda_runtime.h>
#include <cstdint>

#define NTRIP 55
#define DTOT  404480
#define EPSV  1e-6f
#define NKB   395
#define KSPAN 1024
#define NCH   32

__device__ int   d_l1[NTRIP], d_l2[NTRIP], d_l3a[NTRIP], d_widx[NTRIP], d_based[NTRIP];
__device__ float d_sumsq[64 * 9];
__device__ float d_sum0[64];
__device__ float d_y[64 * 800];
__device__ float d_z[64LL * DTOT];
__device__ float d_csq[DTOT];
__device__ float d_csum[DTOT];
__device__ float d_g[DTOT];
__device__ float d_m[5120];
__device__ float d_part[(long)NKB * 8192];

__device__ __forceinline__ float tf32r(float x) {
    asm("cvt.rna.tf32.f32 %0, %0;" : "+f"(x));
    return x;
}

// LN+power affine per (b, l3) recomputed locally from global stats (replaces k_scal)
__device__ __forceinline__ void computeAD(int b, int l3v, float& A, float& D) {
    const int tcnt[9] = {5, 8, 10, 10, 9, 6, 4, 2, 1};
    float power = 0.f;
    #pragma unroll
    for (int l = 0; l < 9; l++) power += d_sumsq[b*9 + l];
    float scale = rsqrtf(power / (float)DTOT + EPSV);
    float cnt = (float)(tcnt[l3v] * 1024 * (2*l3v + 1));
    float ms = scale * scale * d_sumsq[b*9 + l3v] / cnt;
    if (l3v == 0) {
        float mu = scale * d_sum0[b] / cnt;
        float c  = rsqrtf(ms - mu*mu + EPSV);
        A = scale * c; D = -mu * c;
    } else {
        A = scale * rsqrtf(ms + EPSV); D = 0.f;
    }
}

__device__ __forceinline__ int regionOf(long d) {
    if (d < 5120)   return 0;
    if (d < 29696)  return 1;
    if (d < 80896)  return 2;
    if (d < 152576) return 3;
    if (d < 235520) return 4;
    if (d < 303104) return 5;
    if (d < 356352) return 6;
    if (d < 387072) return 7;
    return 8;
}

// ------------- y = Wlin@x (+bias0); block 0 builds tables + zeros stats -------------
__global__ void k_y(const float* __restrict__ x0, const float* __restrict__ x1,
                    const float* __restrict__ x2, const float* __restrict__ x3,
                    const float* __restrict__ x4, const float* __restrict__ Wlin,
                    const float* __restrict__ bias0) {
    int b = blockIdx.x, t = threadIdx.x;
    if (b == 0) {
        if (t == 0) {
            int L1[NTRIP], L2[NTRIP], L3[NTRIP], n = 0;
            for (int l1 = 0; l1 <= 4; l1++)
                for (int l2 = l1; l2 <= 4; l2++)
                    for (int l3 = l2 - l1; l3 <= l1 + l2; l3++) { L1[n]=l1; L2[n]=l2; L3[n]=l3; n++; }
            int idx = 0, based = 0;
            for (int lv = 0; lv <= 8; lv++) {
                for (int s = 0; s < n; s++) if (L3[s] == lv) {
                    d_l1[idx]=L1[s]; d_l2[idx]=L2[s]; d_l3a[idx]=lv; d_widx[idx]=s; d_based[idx]=based;
                    based += 1024 * (2*lv + 1); idx++;
                }
            }
        }
        for (int i = t; i < 64*9; i += blockDim.x) d_sumsq[i] = 0.f;
        for (int i = t; i < 64;   i += blockDim.x) d_sum0[i]  = 0.f;
    }
    const float* xs[5] = {x0, x1, x2, x3, x4};
    const int yo[5] = {0, 32, 128, 288, 512};
    for (int l = 0; l < 5; l++) {
        int M = 2*l + 1;
        const float* x = xs[l] + (long)b * 32 * M;
        for (int e = t; e < 32 * M; e += blockDim.x) {
            int o = e / M, m = e % M;
            float acc = (l == 0) ? bias0[o] : 0.f;
            const float* wr = Wlin + (l*32 + o) * 32;
            #pragma unroll 8
            for (int i = 0; i < 32; i++) acc += wr[i] * x[i*M + m];
            d_y[b*800 + yo[l] + o*M + m] = acc;
        }
    }
}

// ------------- triple products + row-norm + LN stats -------------
// u[i,n,k] = sum_m y1[i,m] w[m,n,k]  (i = y1 channel)
// t[i,j,k] = sum_n y2[j,n] u[i,n,k]  (warp reads u broadcast: i warp-constant, j = lane)
template <int K3>
__device__ __forceinline__ void trip_body(int tr, int b, const float* __restrict__ w3j,
                                          float* sy1, float* sy2, float* sw, float* su,
                                          float* rw1, float* rw2) {
    constexpr int l3v = (K3 - 1) / 2;
    constexpr int K3A = (K3 + 3) & ~3;
    constexpr int NV  = K3A / 4;
    const int l1 = d_l1[tr], l2 = d_l2[tr];
    const int m1 = 2*l1 + 1, n2 = 2*l2 + 1;
    const int yo[5] = {0, 32, 128, 288, 512};
    int t = threadIdx.x, lane = t & 31, w = t >> 5;

    for (int e = t; e < 32*m1; e += 256) sy1[e] = d_y[b*800 + yo[l1] + e];
    for (int e = t; e < 32*n2; e += 256) sy2[e] = d_y[b*800 + yo[l2] + e];
    const float* wp = w3j + (long)d_widx[tr] * 9 * 9 * 17;
    for (int e = t; e < m1*n2*K3; e += 256) {
        int m = e / (n2*K3), r = e % (n2*K3), nn = r / K3, k = r % K3;
        sw[e] = wp[m*153 + nn*17 + k];
    }
    __syncthreads();
    // u-phase
    for (int e = t; e < 32*n2*K3; e += 256) {
        int i = e / (n2*K3), r = e % (n2*K3), nn = r / K3, k = r % K3;
        float a = 0.f;
        for (int m = 0; m < m1; m++) a += sy1[i*m1 + m] * sw[(m*n2 + nn)*K3 + k];
        su[(i*n2 + nn)*K3A + k] = a;
    }
    __syncthreads();

    float lsq = 0.f, ls0 = 0.f;
    long zbase = (long)b * DTOT + d_based[tr];
    for (int p = t; p < 1024; p += 256) {
        int j = p & 31;         // = lane
        int iw = p >> 5;        // warp-constant
        float4 acc4[NV];
        #pragma unroll
        for (int q = 0; q < NV; q++) acc4[q] = make_float4(0.f, 0.f, 0.f, 0.f);
        const float* y2p = &sy2[j*n2];
        for (int n = 0; n < n2; n++) {
            float yn = y2p[n];
            const float4* up = (const float4*)&su[(iw*n2 + n)*K3A];
            #pragma unroll
            for (int q = 0; q < NV; q++) {
                float4 u4 = up[q];
                acc4[q].x += yn*u4.x; acc4[q].y += yn*u4.y;
                acc4[q].z += yn*u4.z; acc4[q].w += yn*u4.w;
            }
        }
        float S = 0.f;
        #pragma unroll
        for (int q = 0; q < NV; q++) {
            if (4*q + 0 < K3) S += acc4[q].x*acc4[q].x;
            if (4*q + 1 < K3) S += acc4[q].y*acc4[q].y;
            if (4*q + 2 < K3) S += acc4[q].z*acc4[q].z;
            if (4*q + 3 < K3) S += acc4[q].w*acc4[q].w;
        }
        float inv = rsqrtf(S + EPSV);
        float* zp = &d_z[zbase + (long)p * K3];
        #pragma unroll
        for (int q = 0; q < NV; q++) {
            if (4*q + 0 < K3) zp[4*q + 0] = acc4[q].x * inv;
            if (4*q + 1 < K3) zp[4*q + 1] = acc4[q].y * inv;
            if (4*q + 2 < K3) zp[4*q + 2] = acc4[q].z * inv;
            if (4*q + 3 < K3) zp[4*q + 3] = acc4[q].w * inv;
        }
        lsq += S * inv * inv;
        if (K3 == 1) ls0 += acc4[0].x * inv;
    }
    // warp shuffle reduce, then cross-warp via smem
    #pragma unroll
    for (int o = 16; o > 0; o >>= 1) {
        lsq += __shfl_xor_sync(0xFFFFFFFFu, lsq, o);
        if (K3 == 1) ls0 += __shfl_xor_sync(0xFFFFFFFFu, ls0, o);
    }
    if (lane == 0) { rw1[w] = lsq; rw2[w] = ls0; }
    __syncthreads();
    if (t == 0) {
        float s1 = 0.f, s2 = 0.f;
        #pragma unroll
        for (int q = 0; q < 8; q++) { s1 += rw1[q]; s2 += rw2[q]; }
        atomicAdd(&d_sumsq[b*9 + l3v], s1);
        if (K3 == 1) atomicAdd(&d_sum0[b], s2);
    }
}

__global__ void __launch_bounds__(256) k_trip_all(const float* __restrict__ w3j) {
    __shared__ float sy1[288], sy2[288], sw[1377];
    __shared__ __align__(16) float su[5760];
    __shared__ float rw1[8], rw2[8];
    int tr = blockIdx.x, b = blockIdx.y;
    switch (d_l3a[tr]) {
        case 0: trip_body<1> (tr, b, w3j, sy1, sy2, sw, su, rw1, rw2); break;
        case 1: trip_body<3> (tr, b, w3j, sy1, sy2, sw, su, rw1, rw2); break;
        case 2: trip_body<5> (tr, b, w3j, sy1, sy2, sw, su, rw1, rw2); break;
        case 3: trip_body<7> (tr, b, w3j, sy1, sy2, sw, su, rw1, rw2); break;
        case 4: trip_body<9> (tr, b, w3j, sy1, sy2, sw, su, rw1, rw2); break;
        case 5: trip_body<11>(tr, b, w3j, sy1, sy2, sw, su, rw1, rw2); break;
        case 6: trip_body<13>(tr, b, w3j, sy1, sy2, sw, su, rw1, rw2); break;
        case 7: trip_body<15>(tr, b, w3j, sy1, sy2, sw, su, rw1, rw2); break;
        case 8: trip_body<17>(tr, b, w3j, sy1, sy2, sw, su, rw1, rw2); break;
    }
}

// ------------- BN column stats: stream z once, per-d csq/csum -------------
__global__ void __launch_bounds__(128) k_bncol() {
    int bid = blockIdx.x, t = threadIdx.x;
    long d0 = (long)bid * 512;
    int l3v = regionOf(d0);
    __shared__ float sA[64], sD[64];
    if (t < 64) computeAD(t, l3v, sA[t], sD[t]);
    __syncthreads();
    long dd = d0 + (long)t * 4;
    float4 sq = make_float4(0.f,0.f,0.f,0.f), sm = make_float4(0.f,0.f,0.f,0.f);
    #pragma unroll 4
    for (int b = 0; b < 64; b++) {
        float4 z4 = *(const float4*)&d_z[(long)b*DTOT + dd];
        float a = sA[b], dv = sD[b];
        float vx = a*z4.x + dv, vy = a*z4.y + dv, vz = a*z4.z + dv, vw = a*z4.w + dv;
        sq.x += vx*vx; sq.y += vy*vy; sq.z += vz*vz; sq.w += vw*vw;
        sm.x += vx;    sm.y += vy;    sm.z += vz;    sm.w += vw;
    }
    *(float4*)&d_csq[dd]  = sq;
    *(float4*)&d_csum[dd] = sm;
}

// ------------- BN reduce: per-(tr,i,j) gain (and mean for l3=0) -------------
__global__ void k_bnred() {
    int id = blockIdx.x, tr = id >> 5, i = id & 31;
    int j = threadIdx.x;
    int l3v = d_l3a[tr], k3 = 2*l3v + 1;
    long base = (long)d_based[tr] + (long)(i*32 + j) * k3;
    float sq = 0.f, sm = 0.f;
    for (int k = 0; k < k3; k++) { sq += d_csq[base + k]; sm += d_csum[base + k]; }
    float gj, mj = 0.f;
    if (l3v == 0) {
        float m = sm * (1.f/64.f);
        gj = rsqrtf(sq*(1.f/64.f) - m*m + EPSV); mj = m;
    } else {
        gj = rsqrtf(sq / (64.f * (float)k3) + EPSV);
    }
    for (int k = 0; k < k3; k++) {
        d_g[base + k] = gj;
        if (l3v == 0) d_m[base + k] = mj;
    }
}

// ------------- split-K GEMM via mma.sync tf32, BN affine fused -------------
__global__ void __launch_bounds__(256, 2) k_gemm_mma(const float* __restrict__ W) {
    __shared__ float As[128][36];
    __shared__ float Bs[64][36];
    __shared__ float sA[64], sD[64];
    int t = threadIdx.x;
    int w = t >> 5, lane = t & 31, gid = lane >> 2, tid4 = lane & 3;
    long kbase = (long)blockIdx.x * KSPAN;
    int l3v = regionOf(kbase);
    bool hasm = (l3v == 0);

    if (t < 64) computeAD(t, l3v, sA[t], sD[t]);
    __syncthreads();

    float c[8][4];
    #pragma unroll
    for (int nt = 0; nt < 8; nt++)
        #pragma unroll
        for (int q = 0; q < 4; q++) c[nt][q] = 0.f;

    float4 av[4], bv[2], gv[2], mv[2];
    {
        long kg = kbase;
        #pragma unroll
        for (int i = 0; i < 4; i++) {
            int id = t + i*256, r = id >> 3, cc = (id & 7) * 4;
            av[i] = *(const float4*)(W + (long)r*DTOT + kg + cc);
        }
        #pragma unroll
        for (int i = 0; i < 2; i++) {
            int id = t + i*256, r = id >> 3, cc = (id & 7) * 4;
            bv[i] = *(const float4*)(d_z + (long)r*DTOT + kg + cc);
            gv[i] = *(const float4*)(d_g + kg + cc);
            mv[i] = hasm ? *(const float4*)(d_m + kg + cc) : make_float4(0.f,0.f,0.f,0.f);
        }
    }

    for (int ch = 0; ch < NCH; ch++) {
        #pragma unroll
        for (int i = 0; i < 4; i++) {
            int id = t + i*256, r = id >> 3, cc = (id & 7) * 4;
            float4 v = av[i];
            v.x = tf32r(v.x); v.y = tf32r(v.y); v.z = tf32r(v.z); v.w = tf32r(v.w);
            *(float4*)&As[r][cc] = v;
        }
        #pragma unroll
        for (int i = 0; i < 2; i++) {
            int id = t + i*256, r = id >> 3, cc = (id & 7) * 4;
            float a = sA[r], dd = sD[r];
            float4 v;
            v.x = tf32r(gv[i].x * (a*bv[i].x + dd - mv[i].x));
            v.y = tf32r(gv[i].y * (a*bv[i].y + dd - mv[i].y));
            v.z = tf32r(gv[i].z * (a*bv[i].z + dd - mv[i].z));
            v.w = tf32r(gv[i].w * (a*bv[i].w + dd - mv[i].w));
            *(float4*)&Bs[r][cc] = v;
        }
        __syncthreads();
        if (ch + 1 < NCH) {
            long kg = kbase + (ch + 1) * 32;
            #pragma unroll
            for (int i = 0; i < 4; i++) {
                int id = t + i*256, r = id >> 3, cc = (id & 7) * 4;
                av[i] = *(const float4*)(W + (long)r*DTOT + kg + cc);
            }
            #pragma unroll
            for (int i = 0; i < 2; i++) {
                int id = t + i*256, r = id >> 3, cc = (id & 7) * 4;
                bv[i] = *(const float4*)(d_z + (long)r*DTOT + kg + cc);
                gv[i] = *(const float4*)(d_g + kg + cc);
                mv[i] = hasm ? *(const float4*)(d_m + kg + cc) : make_float4(0.f,0.f,0.f,0.f);
            }
        }
        #pragma unroll
        for (int ks = 0; ks < 4; ks++) {
            int k0 = ks * 8;
            int ar = w*16 + gid;
            unsigned a0 = __float_as_uint(As[ar][k0 + tid4]);
            unsigned a1 = __float_as_uint(As[ar + 8][k0 + tid4]);
            unsigned a2 = __float_as_uint(As[ar][k0 + tid4 + 4]);
            unsigned a3 = __float_as_uint(As[ar + 8][k0 + tid4 + 4]);
            #pragma unroll
            for (int nt = 0; nt < 8; nt++) {
                unsigned b0 = __float_as_uint(Bs[nt*8 + gid][k0 + tid4]);
                unsigned b1 = __float_as_uint(Bs[nt*8 + gid][k0 + tid4 + 4]);
                asm volatile(
                    "mma.sync.aligned.m16n8k8.row.col.f32.tf32.tf32.f32 "
                    "{%0,%1,%2,%3}, {%4,%5,%6,%7}, {%8,%9}, {%0,%1,%2,%3};"
                    : "+f"(c[nt][0]), "+f"(c[nt][1]), "+f"(c[nt][2]), "+f"(c[nt][3])
                    : "r"(a0), "r"(a1), "r"(a2), "r"(a3), "r"(b0), "r"(b1));
            }
        }
        __syncthreads();
    }

    long pb = (long)blockIdx.x * 8192;
    int j0 = w*16 + gid, n0 = tid4 * 2;
    #pragma unroll
    for (int nt = 0; nt < 8; nt++) {
        int n = nt*8 + n0;
        *(float2*)&d_part[pb + (long)j0*64 + n]       = make_float2(c[nt][0], c[nt][1]);
        *(float2*)&d_part[pb + (long)(j0 + 8)*64 + n] = make_float2(c[nt][2], c[nt][3]);
    }
}

// ------------- reduce partials + bias, split (mu, logvar) -------------
__global__ void k_fin(const float* __restrict__ bfc, float* __restrict__ out) {
    int e = blockIdx.x * blockDim.x + threadIdx.x;
    if (e >= 8192) return;
    float s = 0.f;
    #pragma unroll 8
    for (int blk = 0; blk < NKB; blk++) s += d_part[(long)blk * 8192 + e];
    int j = e >> 6, b = e & 63;
    out[(j >> 6) * 4096 + b*64 + (j & 63)] = s + bfc[j];
}

extern "C" void kernel_launch(void* const* d_in, const int* in_sizes, int n_in,
                              void* d_out, int out_size) {
    const float* x0    = (const float*)d_in[0];
    const float* x1    = (const float*)d_in[1];
    const float* x2    = (const float*)d_in[2];
    const float* x3    = (const float*)d_in[3];
    const float* x4    = (const float*)d_in[4];
    const float* Wlin  = (const float*)d_in[5];
    const float* bias0 = (const float*)d_in[6];
    const float* w3j   = (const float*)d_in[7];
    const float* Wfc   = (const float*)d_in[8];
    const float* bfc   = (const float*)d_in[9];
    float* out = (float*)d_out;

    k_y<<<64, 256>>>(x0, x1, x2, x3, x4, Wlin, bias0);
    k_trip_all<<<dim3(NTRIP, 64), 256>>>(w3j);
    k_bncol<<<DTOT/512, 128>>>();
    k_bnred<<<NTRIP*32, 32>>>();
    k_gemm_mma<<<NKB, 256>>>(Wfc);
    k_fin<<<32, 256>>>(bfc, out);
}